// round 14
// baseline (speedup 1.0000x reference)
#include <cuda_runtime.h>
#include <cuda_fp16.h>
#include <cstdint>

// Shapes: B=64, T=2048, A=D=U=512
// R6: no tcgen05 (compute_103). R8: not LDS-instr-bound. R10: warps alone don't
// help when L1=58%. R11: m32n64 halved LDSM traffic, k_att=299us. R12: 16 warps
// m32n32. R13: k_ctx=44.5us @78% DRAM (rooflined, done). R14: single-barrier
// pipeline in k_att; k_att back in ncu slot.

// ---------------- device scratch ----------------
__device__ __half g_kuT[512 * 512];         // kernel_u transposed [u][k], fp16
__device__ float g_s[64 * 512];             // h@kernel_w + bias_u
__device__ float g_et[64 * 2048];           // et, then at (in place)
__device__ float g_ctx[64 * 512];           // context
__device__ float g_z[64 * 2048];            // gate pre-activations

// ---------------- helpers ----------------
__device__ __forceinline__ uint32_t smem_u32(const void* p) {
    uint32_t a;
    asm("{ .reg .u64 t; cvta.to.shared.u64 t, %1; cvt.u32.u64 %0, t; }" : "=r"(a) : "l"(p));
    return a;
}

// Accurate tanh: 1 - 2/(exp(2x)+1) via ex2+rcp (~2^-22 rel err)
__device__ __forceinline__ float tanhp(float x) {
    float e, r;
    asm("ex2.approx.f32 %0, %1;" : "=f"(e) : "f"(x * 2.88539008177793f));
    asm("rcp.approx.f32 %0, %1;" : "=f"(r) : "f"(e + 1.0f));
    return 1.0f - 2.0f * r;
}

__device__ __forceinline__ void mma16816(float* c,
                                         uint32_t a0, uint32_t a1, uint32_t a2, uint32_t a3,
                                         uint32_t b0, uint32_t b1) {
    asm volatile(
        "mma.sync.aligned.m16n8k16.row.col.f32.f16.f16.f32 "
        "{%0,%1,%2,%3},{%4,%5,%6,%7},{%8,%9},{%0,%1,%2,%3};"
        : "+f"(c[0]), "+f"(c[1]), "+f"(c[2]), "+f"(c[3])
        : "r"(a0), "r"(a1), "r"(a2), "r"(a3), "r"(b0), "r"(b1));
}

__device__ __forceinline__ void ldsm_x4(uint32_t& d0, uint32_t& d1,
                                        uint32_t& d2, uint32_t& d3, uint32_t addr) {
    asm volatile("ldmatrix.sync.aligned.m8n8.x4.shared.b16 {%0,%1,%2,%3}, [%4];"
                 : "=r"(d0), "=r"(d1), "=r"(d2), "=r"(d3) : "r"(addr));
}

__device__ __forceinline__ void cp_async16(uint32_t dst, const void* src) {
    asm volatile("cp.async.cg.shared.global [%0], [%1], 16;"
                 :: "r"(dst), "l"(src) : "memory");
}

// ---------------- kernel P: kernel_u fp32 -> fp16 transposed [u][k] ----------------
__global__ void k_prep(const float* __restrict__ ku) {
    __shared__ float tile[32][33];
    int bx = blockIdx.x & 15, by = blockIdx.x >> 4;
    int tx = threadIdx.x & 31, ty = threadIdx.x >> 5;
#pragma unroll
    for (int j = 0; j < 4; j++)
        tile[ty + j * 8][tx] = ku[(size_t)(bx * 32 + ty + j * 8) * 512 + by * 32 + tx];
    __syncthreads();
#pragma unroll
    for (int j = 0; j < 4; j++)
        g_kuT[(size_t)(by * 32 + ty + j * 8) * 512 + bx * 32 + tx] =
            __float2half(tile[tx][ty + j * 8]);
}

// ---------------- kernel A: s = h @ kernel_w + bias_u ----------------
__global__ void k_s(const float* __restrict__ h, const float* __restrict__ kw,
                    const float* __restrict__ bias) {
    __shared__ float hs[512];
    int b = blockIdx.x, u = threadIdx.x;
    hs[u] = h[b * 512 + u];
    __syncthreads();
    float acc = bias[2048 + u];
#pragma unroll 8
    for (int k = 0; k < 512; k++)
        acc += hs[k] * kw[k * 512 + u];
    g_s[b * 512 + u] = acc;
}

// ---------------- shim: keeps ncu's capture slot on k_att ----------------
__global__ void k_shim() {}

// ---------------- kernel B: attention scores (HMMA, 16 warps, m32n32) ----------------
// Per block: b = blockIdx.y, t0 = blockIdx.x*128.
// 16 chunks of B: (ug 0..3) x (kc 0..3), each 128u x 128k, double-buffered,
// single __syncthreads per chunk.
static constexpr int SA = 520;                   // As row stride (halves)
static constexpr int SB = 136;                   // Bs row stride (halves)
static constexpr int AS_BYTES = 128 * SA * 2;    // 133120
static constexpr int BS_BYTES = 128 * SB * 2;    // 34816
static constexpr int B0_OFF = AS_BYTES;
static constexpr int SV_OFF = AS_BYTES + 2 * BS_BYTES;   // 202752
static constexpr int PART_OFF = SV_OFF + 2 * 512 * 4;    // 206848
static constexpr int SMEM_ATT = PART_OFF + 512 * 4;      // 208896

__global__ __launch_bounds__(512) void k_att(const float* __restrict__ ann,
                                             const float* __restrict__ kv) {
    extern __shared__ char sm[];
    __half* As = (__half*)sm;                               // [128][SA]
    float* s_s = (float*)(sm + SV_OFF);                     // [512]
    float* kv_s = s_s + 512;                                // [512]
    float* part = (float*)(sm + PART_OFF);                  // [4][128]

    int b = blockIdx.y;
    int t0 = blockIdx.x * 128;
    int tid = threadIdx.x;
    uint32_t sb = smem_u32(sm);
    uint32_t bbuf[2] = { sb + B0_OFF, sb + B0_OFF + BS_BYTES };

    if (tid < 512) {
        s_s[tid] = g_s[b * 512 + tid];
        kv_s[tid] = kv[tid];
    }

    int w = tid >> 5;
    int lane = tid & 31;
    int wt = w & 3;       // t-stripe (32 rows at wt*32)
    int wu = w >> 2;      // u-quarter of the 128-u chunk
    int g = lane >> 2;    // row-in-8 (epilogue mapping)
    int tg = lane & 3;    // thread-in-group

    // Stage chunk i (ug=i>>2, kc=i&3): Bs[r][kk] = g_kuT[ug*128+r][kc*128+kk]
    auto stage = [&](int i, uint32_t dst) {
        int ug = i >> 2, kc = i & 3;
        const __half* src = g_kuT + (size_t)(ug * 128) * 512 + kc * 128;
#pragma unroll
        for (int it = 0; it < 4; it++) {
            int idx = tid + it * 512;
            int row = idx >> 4, gi = idx & 15;
            cp_async16(dst + (uint32_t)(row * SB * 2 + gi * 16),
                       src + (size_t)row * 512 + gi * 8);
        }
        asm volatile("cp.async.commit_group;" ::: "memory");
    };

    stage(0, bbuf[0]);   // prefetch chunk 0 before the (long) A conversion

    // Load A tile: ann[b, t0:t0+128, 0:512] fp32 -> fp16 smem
    const float* arow = ann + ((size_t)b * 2048 + t0) * 512;
    for (int i = tid; i < 128 * 128; i += 512) {
        int r = i >> 7;
        int c4 = (i & 127) * 4;
        float4 v = *(const float4*)(arow + (size_t)r * 512 + c4);
        __half2 p0, p1;
        p0.x = __float2half(v.x); p0.y = __float2half(v.y);
        p1.x = __float2half(v.z); p1.y = __float2half(v.w);
        *(__half2*)(As + r * SA + c4) = p0;
        *(__half2*)(As + r * SA + c4 + 2) = p1;
    }

    // ldmatrix per-lane base addresses
    int q = lane >> 3, r8 = lane & 7;
    uint32_t aAddr[2];
#pragma unroll
    for (int mi = 0; mi < 2; mi++)
        aAddr[mi] = sb + (uint32_t)(((wt * 32 + mi * 16 + (q & 1) * 8 + r8) * SA
                                     + (q >> 1) * 8) * 2);
    uint32_t bOff[2];
#pragma unroll
    for (int p = 0; p < 2; p++)
        bOff[p] = (uint32_t)(((wu * 32 + p * 16 + (q >> 1) * 8 + r8) * SB
                              + (q & 1) * 8) * 2);

    float pa[2] = {0.f, 0.f}, pb[2] = {0.f, 0.f};
    float acc[2][4][4];

    for (int i = 0; i < 16; i++) {
        int buf = i & 1, ug = i >> 2, kc = i & 3;

        // chunk i arrived (this thread's groups); prefetched a full chunk ago
        asm volatile("cp.async.wait_group 0;" ::: "memory");
        // visibility of chunk i to all warps + certifies chunk i-1 reads done
        // (consume(i-1) precedes this barrier in program order for every warp);
        // on i=0 also guards the As stores above.
        __syncthreads();
        // restage into chunk i-1's buffer while chunk i is consumed
        if (i + 1 < 16)
            stage(i + 1, bbuf[buf ^ 1]);

        if (kc == 0) {
#pragma unroll
            for (int mi = 0; mi < 2; mi++)
#pragma unroll
                for (int ni = 0; ni < 4; ni++)
#pragma unroll
                    for (int qq = 0; qq < 4; qq++) acc[mi][ni][qq] = 0.f;
        }

        uint32_t bbase = bbuf[buf];
#pragma unroll
        for (int ks = 0; ks < 8; ks++) {
            uint32_t a[2][4];
#pragma unroll
            for (int mi = 0; mi < 2; mi++)
                ldsm_x4(a[mi][0], a[mi][1], a[mi][2], a[mi][3],
                        aAddr[mi] + (uint32_t)((kc * 128 + ks * 16) * 2));
#pragma unroll
            for (int p = 0; p < 2; p++) {
                uint32_t b0, b1, b2, b3;
                ldsm_x4(b0, b1, b2, b3, bbase + bOff[p] + (uint32_t)(ks * 32));
#pragma unroll
                for (int mi = 0; mi < 2; mi++) {
                    mma16816(acc[mi][2 * p],     a[mi][0], a[mi][1], a[mi][2], a[mi][3], b0, b1);
                    mma16816(acc[mi][2 * p + 1], a[mi][0], a[mi][1], a[mi][2], a[mi][3], b2, b3);
                }
            }
        }

        if (kc == 3) {
            // Epilogue: tanh(uh + s) * kv -> row partials
#pragma unroll
            for (int mi = 0; mi < 2; mi++)
#pragma unroll
                for (int ni = 0; ni < 4; ni++) {
                    int ub = ug * 128 + wu * 32 + ni * 8 + tg * 2;
                    float s0 = s_s[ub], s1 = s_s[ub + 1];
                    float v0 = kv_s[ub], v1 = kv_s[ub + 1];
                    pa[mi] += tanhp(acc[mi][ni][0] + s0) * v0 + tanhp(acc[mi][ni][1] + s1) * v1;
                    pb[mi] += tanhp(acc[mi][ni][2] + s0) * v0 + tanhp(acc[mi][ni][3] + s1) * v1;
                }
        }
    }

    // Reduce across the 4 lanes sharing a row, then across u-quarters via smem
#pragma unroll
    for (int mi = 0; mi < 2; mi++) {
        pa[mi] += __shfl_xor_sync(0xffffffffu, pa[mi], 1);
        pa[mi] += __shfl_xor_sync(0xffffffffu, pa[mi], 2);
        pb[mi] += __shfl_xor_sync(0xffffffffu, pb[mi], 1);
        pb[mi] += __shfl_xor_sync(0xffffffffu, pb[mi], 2);
    }
    if (tg == 0) {
#pragma unroll
        for (int mi = 0; mi < 2; mi++) {
            part[wu * 128 + wt * 32 + mi * 16 + g] = pa[mi];
            part[wu * 128 + wt * 32 + mi * 16 + g + 8] = pb[mi];
        }
    }
    __syncthreads();
    if (tid < 128)
        g_et[b * 2048 + t0 + tid] = part[tid] + part[128 + tid]
                                   + part[256 + tid] + part[384 + tid];
}

// ---------------- kernel C: softmax over t (in place), zero ctx ----------------
__global__ void k_softmax() {
    __shared__ float red[512];
    int b = blockIdx.x, tid = threadIdx.x;
    float v[4];
    float mx = -1e30f;
#pragma unroll
    for (int j = 0; j < 4; j++) {
        v[j] = g_et[b * 2048 + j * 512 + tid];
        mx = fmaxf(mx, v[j]);
    }
    red[tid] = mx;
    __syncthreads();
    for (int s = 256; s > 0; s >>= 1) {
        if (tid < s) red[tid] = fmaxf(red[tid], red[tid + s]);
        __syncthreads();
    }
    mx = red[0];
    __syncthreads();
    float sum = 0.f;
#pragma unroll
    for (int j = 0; j < 4; j++) {
        v[j] = expf(v[j] - mx);
        sum += v[j];
    }
    red[tid] = sum;
    __syncthreads();
    for (int s = 256; s > 0; s >>= 1) {
        if (tid < s) red[tid] += red[tid + s];
        __syncthreads();
    }
    float inv = 1.f / red[0];
#pragma unroll
    for (int j = 0; j < 4; j++)
        g_et[b * 2048 + j * 512 + tid] = v[j] * inv;
    g_ctx[b * 512 + tid] = 0.f;
}

// ---------------- kernel D: context = at . annotations (rooflined @78% DRAM) ----------------
__global__ __launch_bounds__(256) void k_ctx(const float* __restrict__ ann) {
    __shared__ float at_s[256];
    int tc = blockIdx.x, b = blockIdx.y;
    int tid = threadIdx.x;
    int tbase = tc * 256;
    at_s[tid] = g_et[b * 2048 + tbase + tid];
    __syncthreads();
    const float2* base = (const float2*)(ann + ((size_t)b * 2048 + tbase) * 512) + tid;
    float ax = 0.f, ay = 0.f;
#pragma unroll 8
    for (int t = 0; t < 256; t++) {
        float2 v = base[(size_t)t * 256];
        float a = at_s[t];
        ax += a * v.x;
        ay += a * v.y;
    }
    atomicAdd(&g_ctx[b * 512 + tid * 2], ax);
    atomicAdd(&g_ctx[b * 512 + tid * 2 + 1], ay);
}

// ---------------- kernel E1: z = [inputs,ctx,h] @ [kernel;rk] + bias ----------------
__global__ __launch_bounds__(256) void k_z(const float* __restrict__ inputs,
                                           const float* __restrict__ h,
                                           const float* __restrict__ kern,
                                           const float* __restrict__ rk,
                                           const float* __restrict__ bias) {
    __shared__ float xs[64][33];
    __shared__ float ws[32][17];
    int j0 = blockIdx.x * 16;
    int tid = threadIdx.x;
    int tj = tid & 7, tb = tid >> 3;
    float acc[2][2] = {};
    for (int kc = 0; kc < 48; kc++) {
        int k0 = kc * 32;
        for (int i = tid; i < 2048; i += 256) {
            int bb = i >> 5, k = i & 31;
            int kk = k0 + k;
            float v;
            if (kk < 512)        v = inputs[bb * 512 + kk];
            else if (kk < 1024)  v = g_ctx[bb * 512 + kk - 512];
            else                 v = h[bb * 512 + kk - 1024];
            xs[bb][k] = v;
        }
        for (int i = tid; i < 512; i += 256) {
            int k = i >> 4, j = i & 15;
            int kk = k0 + k;
            float v = (kk < 1024) ? kern[(size_t)kk * 2048 + j0 + j]
                                  : rk[(size_t)(kk - 1024) * 2048 + j0 + j];
            ws[k][j] = v;
        }
        __syncthreads();
#pragma unroll 8
        for (int k = 0; k < 32; k++) {
            float w0 = ws[k][tj * 2], w1 = ws[k][tj * 2 + 1];
#pragma unroll
            for (int bb = 0; bb < 2; bb++) {
                float x = xs[tb * 2 + bb][k];
                acc[bb][0] += x * w0;
                acc[bb][1] += x * w1;
            }
        }
        __syncthreads();
    }
#pragma unroll
    for (int bb = 0; bb < 2; bb++) {
        int bi = tb * 2 + bb;
        int j = j0 + tj * 2;
        g_z[bi * 2048 + j]     = acc[bb][0] + bias[j];
        g_z[bi * 2048 + j + 1] = acc[bb][1] + bias[j + 1];
    }
}

// ---------------- kernel E2: gates + h_new ----------------
__global__ void k_gate(const float* __restrict__ c, float* __restrict__ out) {
    int b = blockIdx.x, u = threadIdx.x;
    float zi = g_z[b * 2048 + u];
    float zf = g_z[b * 2048 + 512 + u];
    float zg = g_z[b * 2048 + 1024 + u];
    float zo = g_z[b * 2048 + 1536 + u];
    float ig = fminf(fmaxf(0.2f * zi + 0.5f, 0.f), 1.f);
    float fg = fminf(fmaxf(0.2f * zf + 0.5f, 0.f), 1.f);
    float og = fminf(fmaxf(0.2f * zo + 0.5f, 0.f), 1.f);
    float cn = fg * c[b * 512 + u] + ig * tanhf(zg);
    out[b * 512 + u] = og * tanhf(cn);
}

// ---------------- launch ----------------
extern "C" void kernel_launch(void* const* d_in, const int* in_sizes, int n_in,
                              void* d_out, int out_size) {
    const float* inputs = (const float*)d_in[0];
    const float* h      = (const float*)d_in[1];
    const float* c      = (const float*)d_in[2];
    const float* ann    = (const float*)d_in[3];
    const float* kern   = (const float*)d_in[4];
    const float* rk     = (const float*)d_in[5];
    const float* bias   = (const float*)d_in[6];
    const float* ku     = (const float*)d_in[7];
    const float* kw     = (const float*)d_in[8];
    const float* kv     = (const float*)d_in[9];
    float* out = (float*)d_out;

    cudaFuncSetAttribute(k_att, cudaFuncAttributeMaxDynamicSharedMemorySize, SMEM_ATT);

    k_prep<<<256, 256>>>(ku);                     // launch 1
    k_s<<<64, 512>>>(h, kw, bias);                // launch 2
    k_shim<<<1, 32>>>();                          // launch 3
    dim3 gb(16, 64);
    k_att<<<gb, 512, SMEM_ATT>>>(ann, kv);        // launch 4 <- ncu capture slot
    k_softmax<<<64, 512>>>();                     // launch 5
    dim3 gd(8, 64);
    k_ctx<<<gd, 256>>>(ann);                      // launch 6
    k_z<<<128, 256>>>(inputs, h, kern, rk, bias); // launch 7
    k_gate<<<64, 512>>>(c, out);                  // launch 8
}

// round 15
// speedup vs baseline: 1.0408x; 1.0408x over previous
#include <cuda_runtime.h>
#include <cuda_fp16.h>
#include <cstdint>

// Shapes: B=64, T=2048, A=D=U=512
// R6: no tcgen05 (compute_103). R8: not LDS-instr-bound. R11: m32n64 cut LDSM
// traffic. R13: k_ctx rooflined (78% DRAM). R14: barriers neutral; k_att profile
// tensor 42%/L1 50%/issue 29% -> latency-bound in ONE barrier domain.
// R15: 64-t CTAs, smem 108.5KB -> 2 CTAs/SM, independent pipelines per SM.

// ---------------- device scratch ----------------
__device__ __half g_kuT[512 * 512];         // kernel_u transposed [u][k], fp16
__device__ float g_s[64 * 512];             // h@kernel_w + bias_u
__device__ float g_et[64 * 2048];           // et, then at (in place)
__device__ float g_ctx[64 * 512];           // context
__device__ float g_z[64 * 2048];            // gate pre-activations

// ---------------- helpers ----------------
__device__ __forceinline__ uint32_t smem_u32(const void* p) {
    uint32_t a;
    asm("{ .reg .u64 t; cvta.to.shared.u64 t, %1; cvt.u32.u64 %0, t; }" : "=r"(a) : "l"(p));
    return a;
}

// Accurate tanh: 1 - 2/(exp(2x)+1) via ex2+rcp (~2^-22 rel err)
__device__ __forceinline__ float tanhp(float x) {
    float e, r;
    asm("ex2.approx.f32 %0, %1;" : "=f"(e) : "f"(x * 2.88539008177793f));
    asm("rcp.approx.f32 %0, %1;" : "=f"(r) : "f"(e + 1.0f));
    return 1.0f - 2.0f * r;
}

__device__ __forceinline__ void mma16816(float* c,
                                         uint32_t a0, uint32_t a1, uint32_t a2, uint32_t a3,
                                         uint32_t b0, uint32_t b1) {
    asm volatile(
        "mma.sync.aligned.m16n8k16.row.col.f32.f16.f16.f32 "
        "{%0,%1,%2,%3},{%4,%5,%6,%7},{%8,%9},{%0,%1,%2,%3};"
        : "+f"(c[0]), "+f"(c[1]), "+f"(c[2]), "+f"(c[3])
        : "r"(a0), "r"(a1), "r"(a2), "r"(a3), "r"(b0), "r"(b1));
}

__device__ __forceinline__ void ldsm_x4(uint32_t& d0, uint32_t& d1,
                                        uint32_t& d2, uint32_t& d3, uint32_t addr) {
    asm volatile("ldmatrix.sync.aligned.m8n8.x4.shared.b16 {%0,%1,%2,%3}, [%4];"
                 : "=r"(d0), "=r"(d1), "=r"(d2), "=r"(d3) : "r"(addr));
}

__device__ __forceinline__ void cp_async16(uint32_t dst, const void* src) {
    asm volatile("cp.async.cg.shared.global [%0], [%1], 16;"
                 :: "r"(dst), "l"(src) : "memory");
}

// ---------------- kernel P: kernel_u fp32 -> fp16 transposed [u][k] ----------------
__global__ void k_prep(const float* __restrict__ ku) {
    __shared__ float tile[32][33];
    int bx = blockIdx.x & 15, by = blockIdx.x >> 4;
    int tx = threadIdx.x & 31, ty = threadIdx.x >> 5;
#pragma unroll
    for (int j = 0; j < 4; j++)
        tile[ty + j * 8][tx] = ku[(size_t)(bx * 32 + ty + j * 8) * 512 + by * 32 + tx];
    __syncthreads();
#pragma unroll
    for (int j = 0; j < 4; j++)
        g_kuT[(size_t)(by * 32 + ty + j * 8) * 512 + bx * 32 + tx] =
            __float2half(tile[tx][ty + j * 8]);
}

// ---------------- kernel A: s = h @ kernel_w + bias_u ----------------
__global__ void k_s(const float* __restrict__ h, const float* __restrict__ kw,
                    const float* __restrict__ bias) {
    __shared__ float hs[512];
    int b = blockIdx.x, u = threadIdx.x;
    hs[u] = h[b * 512 + u];
    __syncthreads();
    float acc = bias[2048 + u];
#pragma unroll 8
    for (int k = 0; k < 512; k++)
        acc += hs[k] * kw[k * 512 + u];
    g_s[b * 512 + u] = acc;
}

// ---------------- shim: keeps ncu's capture slot on k_att ----------------
__global__ void k_shim() {}

// ---------------- kernel B: attention scores (HMMA, 64-t CTAs, 2/SM) ----------------
// Per block: b = blockIdx.y, t0 = blockIdx.x*64. 8 warps: wt=w&1 (32 t-rows),
// wu=w>>1 (u-quarter). 32 chunks of B: (ug 0..3) x (kc 0..7), each 128u x 64k,
// double-buffered, one __syncthreads per chunk.
static constexpr int TM = 64;                    // t-rows per CTA
static constexpr int SA = 520;                   // As row stride (halves)
static constexpr int SB = 72;                    // Bs row stride (halves)
static constexpr int AS_BYTES = TM * SA * 2;     // 66560
static constexpr int BS_BYTES = 128 * SB * 2;    // 18432
static constexpr int B0_OFF = AS_BYTES;
static constexpr int SV_OFF = AS_BYTES + 2 * BS_BYTES;   // 103424
static constexpr int PART_OFF = SV_OFF + 2 * 512 * 4;    // 107520
static constexpr int SMEM_ATT = PART_OFF + 256 * 4;      // 108544 -> 2 CTAs/SM

__global__ __launch_bounds__(256, 2) void k_att(const float* __restrict__ ann,
                                                const float* __restrict__ kv) {
    extern __shared__ char sm[];
    __half* As = (__half*)sm;                               // [64][SA]
    float* s_s = (float*)(sm + SV_OFF);                     // [512]
    float* kv_s = s_s + 512;                                // [512]
    float* part = (float*)(sm + PART_OFF);                  // [4][64]

    int b = blockIdx.y;
    int t0 = blockIdx.x * TM;
    int tid = threadIdx.x;
    uint32_t sb = smem_u32(sm);
    uint32_t bbuf[2] = { sb + B0_OFF, sb + B0_OFF + BS_BYTES };

    for (int i = tid; i < 512; i += 256) {
        s_s[i] = g_s[b * 512 + i];
        kv_s[i] = kv[i];
    }

    int w = tid >> 5;
    int lane = tid & 31;
    int wt = w & 1;       // t-stripe (32 rows at wt*32)
    int wu = w >> 1;      // u-quarter of the 128-u chunk
    int g = lane >> 2;    // row-in-8 (epilogue mapping)
    int tg = lane & 3;    // thread-in-group

    // Stage chunk i (ug=i>>3, kc=i&7): Bs[r][kk] = g_kuT[ug*128+r][kc*64+kk]
    auto stage = [&](int i, uint32_t dst) {
        int ug = i >> 3, kc = i & 7;
        const __half* src = g_kuT + (size_t)(ug * 128) * 512 + kc * 64;
#pragma unroll
        for (int it = 0; it < 4; it++) {
            int idx = tid + it * 256;
            int row = idx >> 3, gi = idx & 7;
            cp_async16(dst + (uint32_t)(row * SB * 2 + gi * 16),
                       src + (size_t)row * 512 + gi * 8);
        }
        asm volatile("cp.async.commit_group;" ::: "memory");
    };

    stage(0, bbuf[0]);   // prefetch chunk 0 before the A conversion

    // Load A tile: ann[b, t0:t0+64, 0:512] fp32 -> fp16 smem
    const float* arow = ann + ((size_t)b * 2048 + t0) * 512;
    for (int i = tid; i < TM * 128; i += 256) {
        int r = i >> 7;
        int c4 = (i & 127) * 4;
        float4 v = *(const float4*)(arow + (size_t)r * 512 + c4);
        __half2 p0, p1;
        p0.x = __float2half(v.x); p0.y = __float2half(v.y);
        p1.x = __float2half(v.z); p1.y = __float2half(v.w);
        *(__half2*)(As + r * SA + c4) = p0;
        *(__half2*)(As + r * SA + c4 + 2) = p1;
    }

    // ldmatrix per-lane base addresses
    int q = lane >> 3, r8 = lane & 7;
    uint32_t aAddr[2];
#pragma unroll
    for (int mi = 0; mi < 2; mi++)
        aAddr[mi] = sb + (uint32_t)(((wt * 32 + mi * 16 + (q & 1) * 8 + r8) * SA
                                     + (q >> 1) * 8) * 2);
    uint32_t bOff[2];
#pragma unroll
    for (int p = 0; p < 2; p++)
        bOff[p] = (uint32_t)(((wu * 32 + p * 16 + (q >> 1) * 8 + r8) * SB
                              + (q & 1) * 8) * 2);

    float pa[2] = {0.f, 0.f}, pb[2] = {0.f, 0.f};
    float acc[2][4][4];

    for (int i = 0; i < 32; i++) {
        int buf = i & 1, ug = i >> 3, kc = i & 7;

        // chunk i arrived; prefetched a full chunk ago
        asm volatile("cp.async.wait_group 0;" ::: "memory");
        // visibility of chunk i to all warps + certifies chunk i-1 reads done
        // (on i=0 also guards the As / s_s stores above)
        __syncthreads();
        if (i + 1 < 32)
            stage(i + 1, bbuf[buf ^ 1]);

        if (kc == 0) {
#pragma unroll
            for (int mi = 0; mi < 2; mi++)
#pragma unroll
                for (int ni = 0; ni < 4; ni++)
#pragma unroll
                    for (int qq = 0; qq < 4; qq++) acc[mi][ni][qq] = 0.f;
        }

        uint32_t bbase = bbuf[buf];
#pragma unroll
        for (int ks = 0; ks < 4; ks++) {
            uint32_t a[2][4];
#pragma unroll
            for (int mi = 0; mi < 2; mi++)
                ldsm_x4(a[mi][0], a[mi][1], a[mi][2], a[mi][3],
                        aAddr[mi] + (uint32_t)((kc * 64 + ks * 16) * 2));
#pragma unroll
            for (int p = 0; p < 2; p++) {
                uint32_t b0, b1, b2, b3;
                ldsm_x4(b0, b1, b2, b3, bbase + bOff[p] + (uint32_t)(ks * 32));
#pragma unroll
                for (int mi = 0; mi < 2; mi++) {
                    mma16816(acc[mi][2 * p],     a[mi][0], a[mi][1], a[mi][2], a[mi][3], b0, b1);
                    mma16816(acc[mi][2 * p + 1], a[mi][0], a[mi][1], a[mi][2], a[mi][3], b2, b3);
                }
            }
        }

        if (kc == 7) {
            // Epilogue: tanh(uh + s) * kv -> row partials
#pragma unroll
            for (int mi = 0; mi < 2; mi++)
#pragma unroll
                for (int ni = 0; ni < 4; ni++) {
                    int ub = ug * 128 + wu * 32 + ni * 8 + tg * 2;
                    float s0 = s_s[ub], s1 = s_s[ub + 1];
                    float v0 = kv_s[ub], v1 = kv_s[ub + 1];
                    pa[mi] += tanhp(acc[mi][ni][0] + s0) * v0 + tanhp(acc[mi][ni][1] + s1) * v1;
                    pb[mi] += tanhp(acc[mi][ni][2] + s0) * v0 + tanhp(acc[mi][ni][3] + s1) * v1;
                }
        }
    }

    // Reduce across the 4 lanes sharing a row, then across u-quarters via smem
#pragma unroll
    for (int mi = 0; mi < 2; mi++) {
        pa[mi] += __shfl_xor_sync(0xffffffffu, pa[mi], 1);
        pa[mi] += __shfl_xor_sync(0xffffffffu, pa[mi], 2);
        pb[mi] += __shfl_xor_sync(0xffffffffu, pb[mi], 1);
        pb[mi] += __shfl_xor_sync(0xffffffffu, pb[mi], 2);
    }
    if (tg == 0) {
#pragma unroll
        for (int mi = 0; mi < 2; mi++) {
            part[wu * 64 + wt * 32 + mi * 16 + g] = pa[mi];
            part[wu * 64 + wt * 32 + mi * 16 + g + 8] = pb[mi];
        }
    }
    __syncthreads();
    if (tid < TM)
        g_et[b * 2048 + t0 + tid] = part[tid] + part[64 + tid]
                                   + part[128 + tid] + part[192 + tid];
}

// ---------------- kernel C: softmax over t (in place), zero ctx ----------------
__global__ void k_softmax() {
    __shared__ float red[512];
    int b = blockIdx.x, tid = threadIdx.x;
    float v[4];
    float mx = -1e30f;
#pragma unroll
    for (int j = 0; j < 4; j++) {
        v[j] = g_et[b * 2048 + j * 512 + tid];
        mx = fmaxf(mx, v[j]);
    }
    red[tid] = mx;
    __syncthreads();
    for (int s = 256; s > 0; s >>= 1) {
        if (tid < s) red[tid] = fmaxf(red[tid], red[tid + s]);
        __syncthreads();
    }
    mx = red[0];
    __syncthreads();
    float sum = 0.f;
#pragma unroll
    for (int j = 0; j < 4; j++) {
        v[j] = expf(v[j] - mx);
        sum += v[j];
    }
    red[tid] = sum;
    __syncthreads();
    for (int s = 256; s > 0; s >>= 1) {
        if (tid < s) red[tid] += red[tid + s];
        __syncthreads();
    }
    float inv = 1.f / red[0];
#pragma unroll
    for (int j = 0; j < 4; j++)
        g_et[b * 2048 + j * 512 + tid] = v[j] * inv;
    g_ctx[b * 512 + tid] = 0.f;
}

// ---------------- kernel D: context = at . annotations (rooflined @78% DRAM) ----------------
__global__ __launch_bounds__(256) void k_ctx(const float* __restrict__ ann) {
    __shared__ float at_s[256];
    int tc = blockIdx.x, b = blockIdx.y;
    int tid = threadIdx.x;
    int tbase = tc * 256;
    at_s[tid] = g_et[b * 2048 + tbase + tid];
    __syncthreads();
    const float2* base = (const float2*)(ann + ((size_t)b * 2048 + tbase) * 512) + tid;
    float ax = 0.f, ay = 0.f;
#pragma unroll 8
    for (int t = 0; t < 256; t++) {
        float2 v = base[(size_t)t * 256];
        float a = at_s[t];
        ax += a * v.x;
        ay += a * v.y;
    }
    atomicAdd(&g_ctx[b * 512 + tid * 2], ax);
    atomicAdd(&g_ctx[b * 512 + tid * 2 + 1], ay);
}

// ---------------- kernel E1: z = [inputs,ctx,h] @ [kernel;rk] + bias ----------------
__global__ __launch_bounds__(256) void k_z(const float* __restrict__ inputs,
                                           const float* __restrict__ h,
                                           const float* __restrict__ kern,
                                           const float* __restrict__ rk,
                                           const float* __restrict__ bias) {
    __shared__ float xs[64][33];
    __shared__ float ws[32][17];
    int j0 = blockIdx.x * 16;
    int tid = threadIdx.x;
    int tj = tid & 7, tb = tid >> 3;
    float acc[2][2] = {};
    for (int kc = 0; kc < 48; kc++) {
        int k0 = kc * 32;
        for (int i = tid; i < 2048; i += 256) {
            int bb = i >> 5, k = i & 31;
            int kk = k0 + k;
            float v;
            if (kk < 512)        v = inputs[bb * 512 + kk];
            else if (kk < 1024)  v = g_ctx[bb * 512 + kk - 512];
            else                 v = h[bb * 512 + kk - 1024];
            xs[bb][k] = v;
        }
        for (int i = tid; i < 512; i += 256) {
            int k = i >> 4, j = i & 15;
            int kk = k0 + k;
            float v = (kk < 1024) ? kern[(size_t)kk * 2048 + j0 + j]
                                  : rk[(size_t)(kk - 1024) * 2048 + j0 + j];
            ws[k][j] = v;
        }
        __syncthreads();
#pragma unroll 8
        for (int k = 0; k < 32; k++) {
            float w0 = ws[k][tj * 2], w1 = ws[k][tj * 2 + 1];
#pragma unroll
            for (int bb = 0; bb < 2; bb++) {
                float x = xs[tb * 2 + bb][k];
                acc[bb][0] += x * w0;
                acc[bb][1] += x * w1;
            }
        }
        __syncthreads();
    }
#pragma unroll
    for (int bb = 0; bb < 2; bb++) {
        int bi = tb * 2 + bb;
        int j = j0 + tj * 2;
        g_z[bi * 2048 + j]     = acc[bb][0] + bias[j];
        g_z[bi * 2048 + j + 1] = acc[bb][1] + bias[j + 1];
    }
}

// ---------------- kernel E2: gates + h_new ----------------
__global__ void k_gate(const float* __restrict__ c, float* __restrict__ out) {
    int b = blockIdx.x, u = threadIdx.x;
    float zi = g_z[b * 2048 + u];
    float zf = g_z[b * 2048 + 512 + u];
    float zg = g_z[b * 2048 + 1024 + u];
    float zo = g_z[b * 2048 + 1536 + u];
    float ig = fminf(fmaxf(0.2f * zi + 0.5f, 0.f), 1.f);
    float fg = fminf(fmaxf(0.2f * zf + 0.5f, 0.f), 1.f);
    float og = fminf(fmaxf(0.2f * zo + 0.5f, 0.f), 1.f);
    float cn = fg * c[b * 512 + u] + ig * tanhf(zg);
    out[b * 512 + u] = og * tanhf(cn);
}

// ---------------- launch ----------------
extern "C" void kernel_launch(void* const* d_in, const int* in_sizes, int n_in,
                              void* d_out, int out_size) {
    const float* inputs = (const float*)d_in[0];
    const float* h      = (const float*)d_in[1];
    const float* c      = (const float*)d_in[2];
    const float* ann    = (const float*)d_in[3];
    const float* kern   = (const float*)d_in[4];
    const float* rk     = (const float*)d_in[5];
    const float* bias   = (const float*)d_in[6];
    const float* ku     = (const float*)d_in[7];
    const float* kw     = (const float*)d_in[8];
    const float* kv     = (const float*)d_in[9];
    float* out = (float*)d_out;

    cudaFuncSetAttribute(k_att, cudaFuncAttributeMaxDynamicSharedMemorySize, SMEM_ATT);

    k_prep<<<256, 256>>>(ku);                     // launch 1
    k_s<<<64, 512>>>(h, kw, bias);                // launch 2
    k_shim<<<1, 32>>>();                          // launch 3
    dim3 gb(32, 64);
    k_att<<<gb, 256, SMEM_ATT>>>(ann, kv);        // launch 4 <- ncu capture slot
    k_softmax<<<64, 512>>>();                     // launch 5
    dim3 gd(8, 64);
    k_ctx<<<gd, 256>>>(ann);                      // launch 6
    k_z<<<128, 256>>>(inputs, h, kern, rk, bias); // launch 7
    k_gate<<<64, 512>>>(c, out);                  // launch 8
}

// round 16
// speedup vs baseline: 1.1328x; 1.0884x over previous
#include <cuda_runtime.h>
#include <cuda_fp16.h>
#include <cstdint>

// Shapes: B=64, T=2048, A=D=U=512
// R6: no tcgen05 (compute_103). R11/R15: k_att latency-bound, 258us @ 2 CTAs/SM.
// R13: k_ctx rooflined. R16: launch-structure attack — 8 launches -> 5
// (prep+s fused, shim dropped, gate fused into z with direct h_new write).

// ---------------- device scratch ----------------
__device__ __half g_kuT[512 * 512];         // kernel_u transposed [u][k], fp16
__device__ float g_s[64 * 512];             // h@kernel_w + bias_u
__device__ float g_et[64 * 2048];           // et, then at (in place)
__device__ float g_ctx[64 * 512];           // context

// ---------------- helpers ----------------
__device__ __forceinline__ uint32_t smem_u32(const void* p) {
    uint32_t a;
    asm("{ .reg .u64 t; cvta.to.shared.u64 t, %1; cvt.u32.u64 %0, t; }" : "=r"(a) : "l"(p));
    return a;
}

// Accurate tanh: 1 - 2/(exp(2x)+1) via ex2+rcp (~2^-22 rel err)
__device__ __forceinline__ float tanhp(float x) {
    float e, r;
    asm("ex2.approx.f32 %0, %1;" : "=f"(e) : "f"(x * 2.88539008177793f));
    asm("rcp.approx.f32 %0, %1;" : "=f"(r) : "f"(e + 1.0f));
    return 1.0f - 2.0f * r;
}

__device__ __forceinline__ void mma16816(float* c,
                                         uint32_t a0, uint32_t a1, uint32_t a2, uint32_t a3,
                                         uint32_t b0, uint32_t b1) {
    asm volatile(
        "mma.sync.aligned.m16n8k16.row.col.f32.f16.f16.f32 "
        "{%0,%1,%2,%3},{%4,%5,%6,%7},{%8,%9},{%0,%1,%2,%3};"
        : "+f"(c[0]), "+f"(c[1]), "+f"(c[2]), "+f"(c[3])
        : "r"(a0), "r"(a1), "r"(a2), "r"(a3), "r"(b0), "r"(b1));
}

__device__ __forceinline__ void ldsm_x4(uint32_t& d0, uint32_t& d1,
                                        uint32_t& d2, uint32_t& d3, uint32_t addr) {
    asm volatile("ldmatrix.sync.aligned.m8n8.x4.shared.b16 {%0,%1,%2,%3}, [%4];"
                 : "=r"(d0), "=r"(d1), "=r"(d2), "=r"(d3) : "r"(addr));
}

__device__ __forceinline__ void cp_async16(uint32_t dst, const void* src) {
    asm volatile("cp.async.cg.shared.global [%0], [%1], 16;"
                 :: "r"(dst), "l"(src) : "memory");
}

// ---------------- fused: prep (blocks 0..255) + s (blocks 256..319) ----------------
__global__ __launch_bounds__(512) void k_prep_s(const float* __restrict__ ku,
                                                const float* __restrict__ h,
                                                const float* __restrict__ kw,
                                                const float* __restrict__ bias) {
    __shared__ float sbuf[32 * 33];
    int tid = threadIdx.x;
    if (blockIdx.x < 256) {
        float (*tile)[33] = (float (*)[33])sbuf;
        int bx = blockIdx.x & 15, by = blockIdx.x >> 4;
        int tx = tid & 31, ty = tid >> 5;   // 32 x 16
#pragma unroll
        for (int j = 0; j < 2; j++)
            tile[ty + j * 16][tx] = ku[(size_t)(bx * 32 + ty + j * 16) * 512 + by * 32 + tx];
        __syncthreads();
#pragma unroll
        for (int j = 0; j < 2; j++)
            g_kuT[(size_t)(by * 32 + ty + j * 16) * 512 + bx * 32 + tx] =
                __float2half(tile[tx][ty + j * 16]);
    } else {
        float* hs = sbuf;
        int b = blockIdx.x - 256, u = tid;
        hs[u & 511] = h[b * 512 + (u & 511)];
        __syncthreads();
        float acc = bias[2048 + u];
#pragma unroll 8
        for (int k = 0; k < 512; k++)
            acc += hs[k] * kw[k * 512 + u];
        g_s[b * 512 + u] = acc;
    }
}

// ---------------- kernel B: attention scores (HMMA, 64-t CTAs, 2/SM) ----------------
static constexpr int TM = 64;                    // t-rows per CTA
static constexpr int SA = 520;                   // As row stride (halves)
static constexpr int SB = 72;                    // Bs row stride (halves)
static constexpr int AS_BYTES = TM * SA * 2;     // 66560
static constexpr int BS_BYTES = 128 * SB * 2;    // 18432
static constexpr int B0_OFF = AS_BYTES;
static constexpr int SV_OFF = AS_BYTES + 2 * BS_BYTES;   // 103424
static constexpr int PART_OFF = SV_OFF + 2 * 512 * 4;    // 107520
static constexpr int SMEM_ATT = PART_OFF + 256 * 4;      // 108544 -> 2 CTAs/SM

__global__ __launch_bounds__(256, 2) void k_att(const float* __restrict__ ann,
                                                const float* __restrict__ kv) {
    extern __shared__ char sm[];
    __half* As = (__half*)sm;                               // [64][SA]
    float* s_s = (float*)(sm + SV_OFF);                     // [512]
    float* kv_s = s_s + 512;                                // [512]
    float* part = (float*)(sm + PART_OFF);                  // [4][64]

    int b = blockIdx.y;
    int t0 = blockIdx.x * TM;
    int tid = threadIdx.x;
    uint32_t sb = smem_u32(sm);
    uint32_t bbuf[2] = { sb + B0_OFF, sb + B0_OFF + BS_BYTES };

    for (int i = tid; i < 512; i += 256) {
        s_s[i] = g_s[b * 512 + i];
        kv_s[i] = kv[i];
    }

    int w = tid >> 5;
    int lane = tid & 31;
    int wt = w & 1;       // t-stripe (32 rows at wt*32)
    int wu = w >> 1;      // u-quarter of the 128-u chunk
    int g = lane >> 2;    // row-in-8 (epilogue mapping)
    int tg = lane & 3;    // thread-in-group

    // Stage chunk i (ug=i>>3, kc=i&7): Bs[r][kk] = g_kuT[ug*128+r][kc*64+kk]
    auto stage = [&](int i, uint32_t dst) {
        int ug = i >> 3, kc = i & 7;
        const __half* src = g_kuT + (size_t)(ug * 128) * 512 + kc * 64;
#pragma unroll
        for (int it = 0; it < 4; it++) {
            int idx = tid + it * 256;
            int row = idx >> 3, gi = idx & 7;
            cp_async16(dst + (uint32_t)(row * SB * 2 + gi * 16),
                       src + (size_t)row * 512 + gi * 8);
        }
        asm volatile("cp.async.commit_group;" ::: "memory");
    };

    stage(0, bbuf[0]);   // prefetch chunk 0 before the A conversion

    // Load A tile: ann[b, t0:t0+64, 0:512] fp32 -> fp16 smem
    const float* arow = ann + ((size_t)b * 2048 + t0) * 512;
    for (int i = tid; i < TM * 128; i += 256) {
        int r = i >> 7;
        int c4 = (i & 127) * 4;
        float4 v = *(const float4*)(arow + (size_t)r * 512 + c4);
        __half2 p0, p1;
        p0.x = __float2half(v.x); p0.y = __float2half(v.y);
        p1.x = __float2half(v.z); p1.y = __float2half(v.w);
        *(__half2*)(As + r * SA + c4) = p0;
        *(__half2*)(As + r * SA + c4 + 2) = p1;
    }

    // ldmatrix per-lane base addresses
    int q = lane >> 3, r8 = lane & 7;
    uint32_t aAddr[2];
#pragma unroll
    for (int mi = 0; mi < 2; mi++)
        aAddr[mi] = sb + (uint32_t)(((wt * 32 + mi * 16 + (q & 1) * 8 + r8) * SA
                                     + (q >> 1) * 8) * 2);
    uint32_t bOff[2];
#pragma unroll
    for (int p = 0; p < 2; p++)
        bOff[p] = (uint32_t)(((wu * 32 + p * 16 + (q >> 1) * 8 + r8) * SB
                              + (q & 1) * 8) * 2);

    float pa[2] = {0.f, 0.f}, pb[2] = {0.f, 0.f};
    float acc[2][4][4];

    for (int i = 0; i < 32; i++) {
        int buf = i & 1, ug = i >> 3, kc = i & 7;

        asm volatile("cp.async.wait_group 0;" ::: "memory");
        __syncthreads();
        if (i + 1 < 32)
            stage(i + 1, bbuf[buf ^ 1]);

        if (kc == 0) {
#pragma unroll
            for (int mi = 0; mi < 2; mi++)
#pragma unroll
                for (int ni = 0; ni < 4; ni++)
#pragma unroll
                    for (int qq = 0; qq < 4; qq++) acc[mi][ni][qq] = 0.f;
        }

        uint32_t bbase = bbuf[buf];
#pragma unroll
        for (int ks = 0; ks < 4; ks++) {
            uint32_t a[2][4];
#pragma unroll
            for (int mi = 0; mi < 2; mi++)
                ldsm_x4(a[mi][0], a[mi][1], a[mi][2], a[mi][3],
                        aAddr[mi] + (uint32_t)((kc * 64 + ks * 16) * 2));
#pragma unroll
            for (int p = 0; p < 2; p++) {
                uint32_t b0, b1, b2, b3;
                ldsm_x4(b0, b1, b2, b3, bbase + bOff[p] + (uint32_t)(ks * 32));
#pragma unroll
                for (int mi = 0; mi < 2; mi++) {
                    mma16816(acc[mi][2 * p],     a[mi][0], a[mi][1], a[mi][2], a[mi][3], b0, b1);
                    mma16816(acc[mi][2 * p + 1], a[mi][0], a[mi][1], a[mi][2], a[mi][3], b2, b3);
                }
            }
        }

        if (kc == 7) {
#pragma unroll
            for (int mi = 0; mi < 2; mi++)
#pragma unroll
                for (int ni = 0; ni < 4; ni++) {
                    int ub = ug * 128 + wu * 32 + ni * 8 + tg * 2;
                    float s0 = s_s[ub], s1 = s_s[ub + 1];
                    float v0 = kv_s[ub], v1 = kv_s[ub + 1];
                    pa[mi] += tanhp(acc[mi][ni][0] + s0) * v0 + tanhp(acc[mi][ni][1] + s1) * v1;
                    pb[mi] += tanhp(acc[mi][ni][2] + s0) * v0 + tanhp(acc[mi][ni][3] + s1) * v1;
                }
        }
    }

    // Reduce across the 4 lanes sharing a row, then across u-quarters via smem
#pragma unroll
    for (int mi = 0; mi < 2; mi++) {
        pa[mi] += __shfl_xor_sync(0xffffffffu, pa[mi], 1);
        pa[mi] += __shfl_xor_sync(0xffffffffu, pa[mi], 2);
        pb[mi] += __shfl_xor_sync(0xffffffffu, pb[mi], 1);
        pb[mi] += __shfl_xor_sync(0xffffffffu, pb[mi], 2);
    }
    if (tg == 0) {
#pragma unroll
        for (int mi = 0; mi < 2; mi++) {
            part[wu * 64 + wt * 32 + mi * 16 + g] = pa[mi];
            part[wu * 64 + wt * 32 + mi * 16 + g + 8] = pb[mi];
        }
    }
    __syncthreads();
    if (tid < TM)
        g_et[b * 2048 + t0 + tid] = part[tid] + part[64 + tid]
                                   + part[128 + tid] + part[192 + tid];
}

// ---------------- kernel C: softmax over t (in place), zero ctx ----------------
__global__ void k_softmax() {
    __shared__ float red[512];
    int b = blockIdx.x, tid = threadIdx.x;
    float v[4];
    float mx = -1e30f;
#pragma unroll
    for (int j = 0; j < 4; j++) {
        v[j] = g_et[b * 2048 + j * 512 + tid];
        mx = fmaxf(mx, v[j]);
    }
    red[tid] = mx;
    __syncthreads();
    for (int s = 256; s > 0; s >>= 1) {
        if (tid < s) red[tid] = fmaxf(red[tid], red[tid + s]);
        __syncthreads();
    }
    mx = red[0];
    __syncthreads();
    float sum = 0.f;
#pragma unroll
    for (int j = 0; j < 4; j++) {
        v[j] = expf(v[j] - mx);
        sum += v[j];
    }
    red[tid] = sum;
    __syncthreads();
    for (int s = 256; s > 0; s >>= 1) {
        if (tid < s) red[tid] += red[tid + s];
        __syncthreads();
    }
    float inv = 1.f / red[0];
#pragma unroll
    for (int j = 0; j < 4; j++)
        g_et[b * 2048 + j * 512 + tid] = v[j] * inv;
    g_ctx[b * 512 + tid] = 0.f;
}

// ---------------- kernel D: context = at . annotations (rooflined @78% DRAM) ----------------
__global__ __launch_bounds__(256) void k_ctx(const float* __restrict__ ann) {
    __shared__ float at_s[256];
    int tc = blockIdx.x, b = blockIdx.y;
    int tid = threadIdx.x;
    int tbase = tc * 256;
    at_s[tid] = g_et[b * 2048 + tbase + tid];
    __syncthreads();
    const float2* base = (const float2*)(ann + ((size_t)b * 2048 + tbase) * 512) + tid;
    float ax = 0.f, ay = 0.f;
#pragma unroll 8
    for (int t = 0; t < 256; t++) {
        float2 v = base[(size_t)t * 256];
        float a = at_s[t];
        ax += a * v.x;
        ay += a * v.y;
    }
    atomicAdd(&g_ctx[b * 512 + tid * 2], ax);
    atomicAdd(&g_ctx[b * 512 + tid * 2 + 1], ay);
}

// ---------------- kernel E: z + gates + h_new fused ----------------
// grid = (jg 0..31) x (bh 0..3) = 128 blocks, 256 threads.
// Block owns u-cols jg*16..+15 across ALL 4 gates, b-range bh*16..+15.
// Thread (tj=u-col, tb=b) accumulates all 4 gate dot-products -> writes h_new.
__global__ __launch_bounds__(256) void k_zg(const float* __restrict__ inputs,
                                            const float* __restrict__ h,
                                            const float* __restrict__ kern,
                                            const float* __restrict__ rk,
                                            const float* __restrict__ bias,
                                            const float* __restrict__ c,
                                            float* __restrict__ out) {
    __shared__ float xs[16][33];
    __shared__ float ws[32][65];
    int jg = blockIdx.x & 31;
    int bh = blockIdx.x >> 5;
    int tid = threadIdx.x;
    int tj = tid & 15;     // u-col within group
    int tb = tid >> 4;     // b within quarter
    float acc[4] = {0.f, 0.f, 0.f, 0.f};
    for (int kc = 0; kc < 48; kc++) {
        int k0 = kc * 32;
        for (int i = tid; i < 512; i += 256) {
            int bb = i >> 5, k = i & 31;
            int kk = k0 + k;
            int bi = bh * 16 + bb;
            float v;
            if (kk < 512)        v = inputs[bi * 512 + kk];
            else if (kk < 1024)  v = g_ctx[bi * 512 + kk - 512];
            else                 v = h[bi * 512 + kk - 1024];
            xs[bb][k] = v;
        }
        for (int i = tid; i < 2048; i += 256) {
            int k = i >> 6, cc = i & 63;
            int gate = cc >> 4, col = cc & 15;
            int kk = k0 + k;
            int j = gate * 512 + jg * 16 + col;
            float v = (kk < 1024) ? kern[(size_t)kk * 2048 + j]
                                  : rk[(size_t)(kk - 1024) * 2048 + j];
            ws[k][cc] = v;
        }
        __syncthreads();
#pragma unroll 8
        for (int k = 0; k < 32; k++) {
            float x = xs[tb][k];
            acc[0] += x * ws[k][tj];
            acc[1] += x * ws[k][16 + tj];
            acc[2] += x * ws[k][32 + tj];
            acc[3] += x * ws[k][48 + tj];
        }
        __syncthreads();
    }
    int bi = bh * 16 + tb;
    int u = jg * 16 + tj;
    float zi = acc[0] + bias[u];
    float zf = acc[1] + bias[512 + u];
    float zg = acc[2] + bias[1024 + u];
    float zo = acc[3] + bias[1536 + u];
    float ig = fminf(fmaxf(0.2f * zi + 0.5f, 0.f), 1.f);
    float fg = fminf(fmaxf(0.2f * zf + 0.5f, 0.f), 1.f);
    float og = fminf(fmaxf(0.2f * zo + 0.5f, 0.f), 1.f);
    float cn = fg * c[bi * 512 + u] + ig * tanhf(zg);
    out[bi * 512 + u] = og * tanhf(cn);
}

// ---------------- launch ----------------
extern "C" void kernel_launch(void* const* d_in, const int* in_sizes, int n_in,
                              void* d_out, int out_size) {
    const float* inputs = (const float*)d_in[0];
    const float* h      = (const float*)d_in[1];
    const float* c      = (const float*)d_in[2];
    const float* ann    = (const float*)d_in[3];
    const float* kern   = (const float*)d_in[4];
    const float* rk     = (const float*)d_in[5];
    const float* bias   = (const float*)d_in[6];
    const float* ku     = (const float*)d_in[7];
    const float* kw     = (const float*)d_in[8];
    const float* kv     = (const float*)d_in[9];
    float* out = (float*)d_out;

    cudaFuncSetAttribute(k_att, cudaFuncAttributeMaxDynamicSharedMemorySize, SMEM_ATT);

    k_prep_s<<<320, 512>>>(ku, h, kw, bias);               // launch 1
    dim3 gb(32, 64);
    k_att<<<gb, 256, SMEM_ATT>>>(ann, kv);                 // launch 2
    k_softmax<<<64, 512>>>();                              // launch 3
    dim3 gd(8, 64);
    k_ctx<<<gd, 256>>>(ann);                               // launch 4 <- ncu slot
    k_zg<<<128, 256>>>(inputs, h, kern, rk, bias, c, out); // launch 5
}